// round 8
// baseline (speedup 1.0000x reference)
#include <cuda_runtime.h>
#include <cuda_bf16.h>
#include <cstdint>
#include <cfloat>

#define BB 32
#define DD 256
#define SS 2048
#define NN (BB*SS)   // 65536 rows
#define KK 4096      // codes

#define MARGIN 8e-4f
#define CAP 64

// ---------------- device globals (no allocs allowed) ----------------
__device__ float g_enorm[KK];                 // ||e_k||^2
__device__ float g_rx[NN];                    // ||x_n||^2
__device__ int   g_idx[NN];                   // argmin indices
__device__ float g_rowsq[NN];                 // per-row sum (q-x)^2
__device__ __nv_bfloat16 g_ebf[(size_t)KK*DD];   // bf16 codebook [c][d]
__device__ int   g_ccnt[NN];                  // candidate counts
__device__ int   g_cand[(size_t)NN*CAP];      // candidate code ids (16MB)

// ---------------- helpers ----------------
__device__ __forceinline__ uint32_t smem_u32(const void* p) {
    uint32_t a;
    asm("{ .reg .u64 t; cvta.to.shared.u64 t, %1; cvt.u32.u64 %0, t; }" : "=r"(a) : "l"(p));
    return a;
}
__device__ __forceinline__ void ldm_x4(uint32_t (&r)[4], uint32_t addr) {
    asm volatile("ldmatrix.sync.aligned.m8n8.x4.shared.b16 {%0,%1,%2,%3}, [%4];"
        : "=r"(r[0]), "=r"(r[1]), "=r"(r[2]), "=r"(r[3]) : "r"(addr));
}
__device__ __forceinline__ void hmma(float (&d)[4], const uint32_t (&a)[4],
                                     uint32_t b0, uint32_t b1) {
    asm volatile("mma.sync.aligned.m16n8k16.row.col.f32.bf16.bf16.f32 "
        "{%0,%1,%2,%3}, {%4,%5,%6,%7}, {%8,%9}, {%0,%1,%2,%3};"
        : "+f"(d[0]), "+f"(d[1]), "+f"(d[2]), "+f"(d[3])
        : "r"(a[0]), "r"(a[1]), "r"(a[2]), "r"(a[3]), "r"(b0), "r"(b1));
}
// monotone float<->uint encoding for atomicMin over floats
__device__ __forceinline__ unsigned fenc(float f) {
    int b = __float_as_int(f);
    return b >= 0 ? ((unsigned)b | 0x80000000u) : ~(unsigned)b;
}
__device__ __forceinline__ float fdec(unsigned u) {
    int b = (u & 0x80000000u) ? (int)(u ^ 0x80000000u) : ~(int)u;
    return __int_as_float(b);
}

// ---------------- prep kernels ----------------
__global__ void k_enorm(const float* __restrict__ cb) {
    int k = blockIdx.x * blockDim.x + threadIdx.x;
    const float* p = cb + (size_t)k * DD;
    float acc = 0.f;
    for (int d = 0; d < DD; d++) { float v = p[d]; acc = __fadd_rn(acc, __fmul_rn(v, v)); }
    g_enorm[k] = acc;
}

__global__ void k_rx(const float* __restrict__ x) {
    int n = blockIdx.x * blockDim.x + threadIdx.x;
    const float* p = x + (size_t)(n >> 11) * DD * SS + (n & 2047);
    float acc = 0.f;
    for (int d = 0; d < DD; d++) { float v = p[(size_t)d * SS]; acc = __fadd_rn(acc, __fmul_rn(v, v)); }
    g_rx[n] = acc;
    g_ccnt[n] = 0;
}

__global__ void k_ebf(const float* __restrict__ cb) {
    size_t i = (size_t)blockIdx.x * 256 + threadIdx.x;
    g_ebf[i] = __float2bfloat16(cb[i]);
}

// ---------------- K1: bf16 HMMA screen + fused candidate capture ----------
#define XH_STRIDE 264
#define E_STRIDE  40
#define SM_XH     0
#define SM_E0     67584
#define SM_E1     77824
#define SM_K1_TOT 88064

__global__ void __launch_bounds__(256, 2) k_screen(const float* __restrict__ x) {
    extern __shared__ char sm[];
    __shared__ unsigned rmin[128];     // encoded running row-min
    const uint32_t sb = smem_u32(sm);
    const int t = threadIdx.x, lane = t & 31, w = t >> 5;
    const int n0 = blockIdx.x * 128;
    const float* xbase = x + (size_t)(n0 >> 11) * DD * SS + (n0 & 2047);

    if (t < 128) rmin[t] = 0xFFFFFFFFu;

    // build Xh (bf16 rn), coalesced global reads
    for (int i = t; i < 128 * 256; i += 256) {
        int d = i >> 7, r = i & 127;
        float v = __ldg(xbase + (size_t)d * SS + r);
        *(__nv_bfloat16*)(sm + SM_XH + (r * XH_STRIDE + d) * 2) = __float2bfloat16(v);
    }

    const int wr = w & 3, wc = w >> 2;
    const int RB = wr * 32, CB = wc * 64;

    float acc[2][8][4];
    #pragma unroll
    for (int mt = 0; mt < 2; mt++)
        #pragma unroll
        for (int nt = 0; nt < 8; nt++)
            #pragma unroll
            for (int i = 0; i < 4; i++) acc[mt][nt][i] = 0.f;

    const int lc = t >> 1, lh = t & 1;
    uint4 st0, st1;
    {   // prefetch chunk 0
        const char* src = (const char*)(g_ebf + (size_t)lc * 256 + lh * 16);
        st0 = __ldg((const uint4*)src);
        st1 = __ldg((const uint4*)(src + 16));
        char* dst = sm + SM_E0 + (lc * E_STRIDE + lh * 16) * 2;
        *(uint4*)dst = st0; *(uint4*)(dst + 16) = st1;
    }
    __syncthreads();

    const int a_row = (lane & 7) + ((lane >> 3) & 1) * 8;
    const int a_kh  = ((lane >> 4) & 1) * 8;
    const int b_row = (lane & 7) + ((lane >> 4) & 1) * 8;
    const int b_kh  = ((lane >> 3) & 1) * 8;

    int cur = 0;
    for (int ci = 0; ci < 256; ci++) {       // 32 tiles x 8 k-chunks(32)
        const int tt = ci >> 3, kc = ci & 7;
        if (ci + 1 < 256) {
            int t2 = (ci + 1) >> 3, k2 = (ci + 1) & 7;
            const char* src = (const char*)(g_ebf + ((size_t)t2 * 128 + lc) * 256 + k2 * 32 + lh * 16);
            st0 = __ldg((const uint4*)src);
            st1 = __ldg((const uint4*)(src + 16));
        }
        const uint32_t ebase = sb + (cur ? SM_E1 : SM_E0);
        #pragma unroll
        for (int ks = 0; ks < 2; ks++) {
            const int k0 = kc * 32 + ks * 16;
            uint32_t a[2][4];
            #pragma unroll
            for (int mt = 0; mt < 2; mt++)
                ldm_x4(a[mt], sb + SM_XH +
                    ((RB + mt * 16 + a_row) * XH_STRIDE + k0 + a_kh) * 2);
            uint32_t bf[4][4];
            #pragma unroll
            for (int p = 0; p < 4; p++)
                ldm_x4(bf[p], ebase +
                    ((CB + p * 16 + b_row) * E_STRIDE + ks * 16 + b_kh) * 2);
            #pragma unroll
            for (int mt = 0; mt < 2; mt++)
                #pragma unroll
                for (int nt = 0; nt < 8; nt++)
                    hmma(acc[mt][nt], a[mt], bf[nt >> 1][(nt & 1) * 2],
                         bf[nt >> 1][(nt & 1) * 2 + 1]);
        }
        if (ci + 1 < 256) {
            char* dst = sm + (cur ? SM_E0 : SM_E1) + (lc * E_STRIDE + lh * 16) * 2;
            *(uint4*)dst = st0; *(uint4*)(dst + 16) = st1;
        }
        // tile epilogue: scores computed ONCE in-place; capture guarded.
        // rmin monotone-decreasing => any read >= final min => captured set
        // is a superset of the true margin set; exact rescue makes the final
        // result invariant to capture-set/timing differences.
        if (kc == 7) {
            const int tb = tt * 128;
            #pragma unroll
            for (int mt = 0; mt < 2; mt++) {
                float mn01 = FLT_MAX, mn23 = FLT_MAX;
                #pragma unroll
                for (int nt = 0; nt < 8; nt++) {
                    const int gcol = tb + CB + nt * 8 + (lane & 3) * 2;
                    float2 ce = __ldg((const float2*)&g_enorm[gcol]);
                    acc[mt][nt][0] = ce.x - 2.f * acc[mt][nt][0];
                    acc[mt][nt][1] = ce.y - 2.f * acc[mt][nt][1];
                    acc[mt][nt][2] = ce.x - 2.f * acc[mt][nt][2];
                    acc[mt][nt][3] = ce.y - 2.f * acc[mt][nt][3];
                    mn01 = fminf(mn01, fminf(acc[mt][nt][0], acc[mt][nt][1]));
                    mn23 = fminf(mn23, fminf(acc[mt][nt][2], acc[mt][nt][3]));
                }
                const int r0 = RB + mt * 16 + (lane >> 2);
                atomicMin(&rmin[r0], fenc(mn01));
                atomicMin(&rmin[r0 + 8], fenc(mn23));
                const float th0 = fdec(rmin[r0]) + MARGIN;
                const float th1 = fdec(rmin[r0 + 8]) + MARGIN;
                if (mn01 <= th0 || mn23 <= th1) {   // rare: record tiles only
                    #pragma unroll
                    for (int nt = 0; nt < 8; nt++) {
                        const int gcol = tb + CB + nt * 8 + (lane & 3) * 2;
                        if (acc[mt][nt][0] <= th0) {
                            int p = atomicAdd(&g_ccnt[n0 + r0], 1);
                            if (p < CAP) g_cand[(size_t)(n0 + r0) * CAP + p] = gcol;
                        }
                        if (acc[mt][nt][1] <= th0) {
                            int p = atomicAdd(&g_ccnt[n0 + r0], 1);
                            if (p < CAP) g_cand[(size_t)(n0 + r0) * CAP + p] = gcol + 1;
                        }
                        if (acc[mt][nt][2] <= th1) {
                            int p = atomicAdd(&g_ccnt[n0 + r0 + 8], 1);
                            if (p < CAP) g_cand[(size_t)(n0 + r0 + 8) * CAP + p] = gcol;
                        }
                        if (acc[mt][nt][3] <= th1) {
                            int p = atomicAdd(&g_ccnt[n0 + r0 + 8], 1);
                            if (p < CAP) g_cand[(size_t)(n0 + r0 + 8) * CAP + p] = gcol + 1;
                        }
                    }
                }
                #pragma unroll
                for (int nt = 0; nt < 8; nt++) {
                    acc[mt][nt][0] = 0.f; acc[mt][nt][1] = 0.f;
                    acc[mt][nt][2] = 0.f; acc[mt][nt][3] = 0.f;
                }
            }
        }
        __syncthreads();
        cur ^= 1;
    }
}

// ---------------- K2: exact rescue + fused per-row loss (warp per row) ----
__global__ void __launch_bounds__(256) k_rescue(const float* __restrict__ x,
                                                const float* __restrict__ cb) {
    const int n = (blockIdx.x * 256 + threadIdx.x) >> 5;
    const int lane = threadIdx.x & 31;
    const float* xp = x + (size_t)(n >> 11) * DD * SS + (n & 2047);

    float xr[8];
    #pragma unroll
    for (int j = 0; j < 8; j++)
        xr[j] = __ldg(xp + (size_t)(lane + 32 * j) * SS);

    int cnt = __ldg(&g_ccnt[n]);
    if (cnt > CAP) cnt = CAP;
    const float rxv = __ldg(&g_rx[n]);

    float bd = FLT_MAX; int bi = 0x7fffffff;
    for (int i = 0; i < cnt; i++) {
        int c = __ldg(&g_cand[(size_t)n * CAP + i]);
        const float* ep = cb + (size_t)c * DD;
        float pa = 0.f;
        #pragma unroll
        for (int j = 0; j < 8; j++)
            pa = fmaf(xr[j], __ldg(ep + lane + 32 * j), pa);
        #pragma unroll
        for (int o = 16; o > 0; o >>= 1)
            pa += __shfl_down_sync(0xFFFFFFFFu, pa, o);
        pa = __shfl_sync(0xFFFFFFFFu, pa, 0);
        float ce = __ldg(&g_enorm[c]);
        float dist = __fsub_rn(__fadd_rn(rxv, ce), __fmul_rn(2.0f, pa));
        if (dist < bd || (dist == bd && c < bi)) { bd = dist; bi = c; }
    }

    // fused loss: sum (q - x)^2 over the row, deterministic shfl reduce
    const float* qp = cb + (size_t)bi * DD;
    float sq = 0.f;
    #pragma unroll
    for (int j = 0; j < 8; j++) {
        float df = __ldg(qp + lane + 32 * j) - xr[j];
        sq = fmaf(df, df, sq);
    }
    #pragma unroll
    for (int o = 16; o > 0; o >>= 1)
        sq += __shfl_down_sync(0xFFFFFFFFu, sq, o);

    if (lane == 0) { g_idx[n] = bi; g_rowsq[n] = sq; }
}

// ---------------- output: pure gather-write (8 d per thread) --------------
__global__ void k_out(const float* __restrict__ cb, float* __restrict__ out) {
    int n = blockIdx.x * 256 + threadIdx.x;
    int d0 = blockIdx.y * 8;
    int idx = __ldg(&g_idx[n]);
    float4 q0 = __ldg((const float4*)(cb + (size_t)idx * DD + d0));
    float4 q1 = __ldg((const float4*)(cb + (size_t)idx * DD + d0 + 4));
    size_t base = (size_t)(n >> 11) * DD * SS + (size_t)d0 * SS + (n & 2047);
    out[base]            = q0.x;
    out[base + SS]       = q0.y;
    out[base + 2 * SS]   = q0.z;
    out[base + 3 * SS]   = q0.w;
    out[base + 4 * SS]   = q1.x;
    out[base + 5 * SS]   = q1.y;
    out[base + 6 * SS]   = q1.z;
    out[base + 7 * SS]   = q1.w;
}

// ---------------- final loss: fixed-order reduction of 65536 row sums -----
__global__ void k_loss(float* __restrict__ out, int out_size) {
    __shared__ double smr[256];
    int t = threadIdx.x;
    double acc = 0.0;
    for (int j = 0; j < 256; j++)
        acc += (double)g_rowsq[t + 256 * j];
    smr[t] = acc;
    __syncthreads();
    #pragma unroll
    for (int s2 = 128; s2 > 0; s2 >>= 1) {
        if (t < s2) smr[t] += smr[t + s2];
        __syncthreads();
    }
    if (t == 0) {
        double mse = smr[0] / (double)((size_t)NN * DD);
        out[out_size - 1] = (float)(1.25 * mse);
    }
}

// ---------------- launch ----------------
extern "C" void kernel_launch(void* const* d_in, const int* in_sizes, int n_in,
                              void* d_out, int out_size) {
    const float* x  = (const float*)d_in[0];
    const float* cb = (const float*)d_in[1];
    float* out = (float*)d_out;

    static bool attr_set = false;
    if (!attr_set) {
        cudaFuncSetAttribute(k_screen, cudaFuncAttributeMaxDynamicSharedMemorySize, SM_K1_TOT);
        attr_set = true;
    }

    k_enorm<<<KK / 256, 256>>>(cb);
    k_rx<<<NN / 256, 256>>>(x);
    k_ebf<<<(KK * DD) / 256, 256>>>(cb);
    k_screen<<<NN / 128, 256, SM_K1_TOT>>>(x);
    k_rescue<<<NN / 8, 256>>>(x, cb);
    k_out<<<dim3(NN / 256, DD / 8), 256>>>(cb, out);
    k_loss<<<1, 256>>>(out, out_size);
}

// round 9
// speedup vs baseline: 1.0442x; 1.0442x over previous
#include <cuda_runtime.h>
#include <cuda_bf16.h>
#include <cstdint>
#include <cfloat>

#define BB 32
#define DD 256
#define SS 2048
#define NN (BB*SS)   // 65536 rows
#define KK 4096      // codes

#define MARGIN 8e-4f
#define CAP 64

// ---------------- device globals (no allocs allowed) ----------------
__device__ float g_enorm[KK];                 // ||e_k||^2
__device__ float g_rx[NN];                    // ||x_n||^2
__device__ int   g_idx[NN];                   // argmin indices
__device__ float g_partial[8192];             // loss partials
__device__ __nv_bfloat16 g_ebf[(size_t)KK*DD];   // bf16 codebook [c][d]
__device__ int   g_ccnt[NN];                  // candidate counts
__device__ int   g_cand[(size_t)NN*CAP];      // candidate code ids (16MB)

// ---------------- helpers ----------------
__device__ __forceinline__ uint32_t smem_u32(const void* p) {
    uint32_t a;
    asm("{ .reg .u64 t; cvta.to.shared.u64 t, %1; cvt.u32.u64 %0, t; }" : "=r"(a) : "l"(p));
    return a;
}
__device__ __forceinline__ void ldm_x4(uint32_t (&r)[4], uint32_t addr) {
    asm volatile("ldmatrix.sync.aligned.m8n8.x4.shared.b16 {%0,%1,%2,%3}, [%4];"
        : "=r"(r[0]), "=r"(r[1]), "=r"(r[2]), "=r"(r[3]) : "r"(addr));
}
__device__ __forceinline__ void hmma(float (&d)[4], const uint32_t (&a)[4],
                                     uint32_t b0, uint32_t b1) {
    asm volatile("mma.sync.aligned.m16n8k16.row.col.f32.bf16.bf16.f32 "
        "{%0,%1,%2,%3}, {%4,%5,%6,%7}, {%8,%9}, {%0,%1,%2,%3};"
        : "+f"(d[0]), "+f"(d[1]), "+f"(d[2]), "+f"(d[3])
        : "r"(a[0]), "r"(a[1]), "r"(a[2]), "r"(a[3]), "r"(b0), "r"(b1));
}
// monotone float<->uint encoding for atomicMin over floats
__device__ __forceinline__ unsigned fenc(float f) {
    int b = __float_as_int(f);
    return b >= 0 ? ((unsigned)b | 0x80000000u) : ~(unsigned)b;
}
__device__ __forceinline__ float fdec(unsigned u) {
    int b = (u & 0x80000000u) ? (int)(u ^ 0x80000000u) : ~(int)u;
    return __int_as_float(b);
}

// ---------------- prep kernels ----------------
__global__ void k_enorm(const float* __restrict__ cb) {
    int k = blockIdx.x * blockDim.x + threadIdx.x;
    const float* p = cb + (size_t)k * DD;
    float acc = 0.f;
    for (int d = 0; d < DD; d++) { float v = p[d]; acc = __fadd_rn(acc, __fmul_rn(v, v)); }
    g_enorm[k] = acc;
}

__global__ void k_rx(const float* __restrict__ x) {
    int n = blockIdx.x * blockDim.x + threadIdx.x;
    const float* p = x + (size_t)(n >> 11) * DD * SS + (n & 2047);
    float acc = 0.f;
    for (int d = 0; d < DD; d++) { float v = p[(size_t)d * SS]; acc = __fadd_rn(acc, __fmul_rn(v, v)); }
    g_rx[n] = acc;
    g_ccnt[n] = 0;
}

__global__ void k_ebf(const float* __restrict__ cb) {
    size_t i = (size_t)blockIdx.x * 256 + threadIdx.x;
    g_ebf[i] = __float2bfloat16(cb[i]);
}

// ---------------- K1: bf16 HMMA screen + fused candidate capture ----------
// k-chunk widened to 64: 128 iterations, sync every 24 LDSM + 64 HMMA.
#define XH_STRIDE 264
#define E_STRIDE  72                     // elements; 144B row stride (bank-clean)
#define SM_XH     0
#define SM_E0     67584
#define SM_E1     86016
#define SM_K1_TOT 104448

__global__ void __launch_bounds__(256, 2) k_screen(const float* __restrict__ x) {
    extern __shared__ char sm[];
    __shared__ unsigned rmin[128];     // encoded running row-min
    const uint32_t sb = smem_u32(sm);
    const int t = threadIdx.x, lane = t & 31, w = t >> 5;
    const int n0 = blockIdx.x * 128;
    const float* xbase = x + (size_t)(n0 >> 11) * DD * SS + (n0 & 2047);

    if (t < 128) rmin[t] = 0xFFFFFFFFu;

    // build Xh (bf16 rn), coalesced global reads
    for (int i = t; i < 128 * 256; i += 256) {
        int d = i >> 7, r = i & 127;
        float v = __ldg(xbase + (size_t)d * SS + r);
        *(__nv_bfloat16*)(sm + SM_XH + (r * XH_STRIDE + d) * 2) = __float2bfloat16(v);
    }

    const int wr = w & 3, wc = w >> 2;
    const int RB = wr * 32, CB = wc * 64;

    float acc[2][8][4];
    #pragma unroll
    for (int mt = 0; mt < 2; mt++)
        #pragma unroll
        for (int nt = 0; nt < 8; nt++)
            #pragma unroll
            for (int i = 0; i < 4; i++) acc[mt][nt][i] = 0.f;

    // B chunk loader: thread covers row lc = t>>1, half lh = t&1 (32 elem = 64B)
    const int lc = t >> 1, lh = t & 1;
    uint4 st[4];
    {   // prefetch chunk 0 (tile 0, kc 0)
        const uint4* src = (const uint4*)(g_ebf + (size_t)lc * 256 + lh * 32);
        #pragma unroll
        for (int q = 0; q < 4; q++) st[q] = __ldg(src + q);
        char* dst = sm + SM_E0 + (lc * E_STRIDE + lh * 32) * 2;
        #pragma unroll
        for (int q = 0; q < 4; q++) *(uint4*)(dst + q * 16) = st[q];
    }
    __syncthreads();

    const int a_row = (lane & 7) + ((lane >> 3) & 1) * 8;
    const int a_kh  = ((lane >> 4) & 1) * 8;
    const int b_row = (lane & 7) + ((lane >> 4) & 1) * 8;
    const int b_kh  = ((lane >> 3) & 1) * 8;

    int cur = 0;
    for (int ci = 0; ci < 128; ci++) {       // 32 tiles x 4 k-chunks(64)
        const int tt = ci >> 2, kc = ci & 3;
        // prefetch next chunk into regs
        if (ci + 1 < 128) {
            int t2 = (ci + 1) >> 2, k2 = (ci + 1) & 3;
            const uint4* src = (const uint4*)(g_ebf +
                ((size_t)t2 * 128 + lc) * 256 + k2 * 64 + lh * 32);
            #pragma unroll
            for (int q = 0; q < 4; q++) st[q] = __ldg(src + q);
        }
        // compute current chunk: 4 k-steps of 16
        const uint32_t ebase = sb + (cur ? SM_E1 : SM_E0);
        #pragma unroll
        for (int ks = 0; ks < 4; ks++) {
            const int k0 = kc * 64 + ks * 16;
            uint32_t a[2][4];
            #pragma unroll
            for (int mt = 0; mt < 2; mt++)
                ldm_x4(a[mt], sb + SM_XH +
                    ((RB + mt * 16 + a_row) * XH_STRIDE + k0 + a_kh) * 2);
            uint32_t bf[4][4];
            #pragma unroll
            for (int p = 0; p < 4; p++)
                ldm_x4(bf[p], ebase +
                    ((CB + p * 16 + b_row) * E_STRIDE + ks * 16 + b_kh) * 2);
            #pragma unroll
            for (int mt = 0; mt < 2; mt++)
                #pragma unroll
                for (int nt = 0; nt < 8; nt++)
                    hmma(acc[mt][nt], a[mt], bf[nt >> 1][(nt & 1) * 2],
                         bf[nt >> 1][(nt & 1) * 2 + 1]);
        }
        // store next chunk
        if (ci + 1 < 128) {
            char* dst = sm + (cur ? SM_E0 : SM_E1) + (lc * E_STRIDE + lh * 32) * 2;
            #pragma unroll
            for (int q = 0; q < 4; q++) *(uint4*)(dst + q * 16) = st[q];
        }
        // tile epilogue: scores in place, capture guarded (superset invariant:
        // rmin monotone decreasing, rescue exact => result race-invariant)
        if (kc == 3) {
            const int tb = tt * 128;
            #pragma unroll
            for (int mt = 0; mt < 2; mt++) {
                float mn01 = FLT_MAX, mn23 = FLT_MAX;
                #pragma unroll
                for (int nt = 0; nt < 8; nt++) {
                    const int gcol = tb + CB + nt * 8 + (lane & 3) * 2;
                    float2 ce = __ldg((const float2*)&g_enorm[gcol]);
                    acc[mt][nt][0] = ce.x - 2.f * acc[mt][nt][0];
                    acc[mt][nt][1] = ce.y - 2.f * acc[mt][nt][1];
                    acc[mt][nt][2] = ce.x - 2.f * acc[mt][nt][2];
                    acc[mt][nt][3] = ce.y - 2.f * acc[mt][nt][3];
                    mn01 = fminf(mn01, fminf(acc[mt][nt][0], acc[mt][nt][1]));
                    mn23 = fminf(mn23, fminf(acc[mt][nt][2], acc[mt][nt][3]));
                }
                const int r0 = RB + mt * 16 + (lane >> 2);
                atomicMin(&rmin[r0], fenc(mn01));
                atomicMin(&rmin[r0 + 8], fenc(mn23));
                const float th0 = fdec(rmin[r0]) + MARGIN;
                const float th1 = fdec(rmin[r0 + 8]) + MARGIN;
                if (mn01 <= th0 || mn23 <= th1) {   // record tiles only
                    #pragma unroll
                    for (int nt = 0; nt < 8; nt++) {
                        const int gcol = tb + CB + nt * 8 + (lane & 3) * 2;
                        if (acc[mt][nt][0] <= th0) {
                            int p = atomicAdd(&g_ccnt[n0 + r0], 1);
                            if (p < CAP) g_cand[(size_t)(n0 + r0) * CAP + p] = gcol;
                        }
                        if (acc[mt][nt][1] <= th0) {
                            int p = atomicAdd(&g_ccnt[n0 + r0], 1);
                            if (p < CAP) g_cand[(size_t)(n0 + r0) * CAP + p] = gcol + 1;
                        }
                        if (acc[mt][nt][2] <= th1) {
                            int p = atomicAdd(&g_ccnt[n0 + r0 + 8], 1);
                            if (p < CAP) g_cand[(size_t)(n0 + r0 + 8) * CAP + p] = gcol;
                        }
                        if (acc[mt][nt][3] <= th1) {
                            int p = atomicAdd(&g_ccnt[n0 + r0 + 8], 1);
                            if (p < CAP) g_cand[(size_t)(n0 + r0 + 8) * CAP + p] = gcol + 1;
                        }
                    }
                }
                #pragma unroll
                for (int nt = 0; nt < 8; nt++) {
                    acc[mt][nt][0] = 0.f; acc[mt][nt][1] = 0.f;
                    acc[mt][nt][2] = 0.f; acc[mt][nt][3] = 0.f;
                }
            }
        }
        __syncthreads();
        cur ^= 1;
    }
}

// ---------------- K2: exact rescue over candidates (warp per row) --------
__global__ void __launch_bounds__(256) k_rescue(const float* __restrict__ x,
                                                const float* __restrict__ cb) {
    const int n = (blockIdx.x * 256 + threadIdx.x) >> 5;
    const int lane = threadIdx.x & 31;
    const float* xp = x + (size_t)(n >> 11) * DD * SS + (n & 2047);

    float xr[8];
    #pragma unroll
    for (int j = 0; j < 8; j++)
        xr[j] = __ldg(xp + (size_t)(lane + 32 * j) * SS);

    int cnt = __ldg(&g_ccnt[n]);
    if (cnt > CAP) cnt = CAP;
    const float rxv = __ldg(&g_rx[n]);

    float bd = FLT_MAX; int bi = 0x7fffffff;
    for (int i = 0; i < cnt; i++) {
        int c = __ldg(&g_cand[(size_t)n * CAP + i]);
        const float* ep = cb + (size_t)c * DD;
        float pa = 0.f;
        #pragma unroll
        for (int j = 0; j < 8; j++)
            pa = fmaf(xr[j], __ldg(ep + lane + 32 * j), pa);
        #pragma unroll
        for (int o = 16; o > 0; o >>= 1)
            pa += __shfl_down_sync(0xFFFFFFFFu, pa, o);
        pa = __shfl_sync(0xFFFFFFFFu, pa, 0);
        float ce = __ldg(&g_enorm[c]);
        float dist = __fsub_rn(__fadd_rn(rxv, ce), __fmul_rn(2.0f, pa));
        if (dist < bd || (dist == bd && c < bi)) { bd = dist; bi = c; }
    }
    if (lane == 0) g_idx[n] = bi;
}

// ---------------- output + loss (R7 version: 8 d per thread) --------------
__global__ void k_out(const float* __restrict__ x, const float* __restrict__ cb,
                      float* __restrict__ out) {
    int n = blockIdx.x * 256 + threadIdx.x;
    int d0 = blockIdx.y * 8;
    int idx = __ldg(&g_idx[n]);
    float4 q0 = __ldg((const float4*)(cb + (size_t)idx * DD + d0));
    float4 q1 = __ldg((const float4*)(cb + (size_t)idx * DD + d0 + 4));
    float q[8] = {q0.x, q0.y, q0.z, q0.w, q1.x, q1.y, q1.z, q1.w};

    size_t base = (size_t)(n >> 11) * DD * SS + (size_t)d0 * SS + (n & 2047);
    float sq = 0.f;
    #pragma unroll
    for (int dd = 0; dd < 8; dd++) {
        size_t addr = base + (size_t)dd * SS;
        float xv = __ldg(&x[addr]);
        out[addr] = q[dd];
        float df = q[dd] - xv;
        sq += df * df;
    }

    __shared__ float smr[256];
    smr[threadIdx.x] = sq;
    __syncthreads();
    #pragma unroll
    for (int s2 = 128; s2 > 0; s2 >>= 1) {
        if (threadIdx.x < s2) smr[threadIdx.x] += smr[threadIdx.x + s2];
        __syncthreads();
    }
    if (threadIdx.x == 0)
        g_partial[blockIdx.y * gridDim.x + blockIdx.x] = smr[0];
}

__global__ void k_loss(float* __restrict__ out, int out_size) {
    __shared__ double smr[256];
    int t = threadIdx.x;
    double acc = 0.0;
    for (int j = 0; j < 32; j++)
        acc += (double)g_partial[t + 256 * j];
    smr[t] = acc;
    __syncthreads();
    #pragma unroll
    for (int s2 = 128; s2 > 0; s2 >>= 1) {
        if (t < s2) smr[t] += smr[t + s2];
        __syncthreads();
    }
    if (t == 0) {
        double mse = smr[0] / (double)((size_t)NN * DD);
        out[out_size - 1] = (float)(1.25 * mse);
    }
}

// ---------------- launch ----------------
extern "C" void kernel_launch(void* const* d_in, const int* in_sizes, int n_in,
                              void* d_out, int out_size) {
    const float* x  = (const float*)d_in[0];
    const float* cb = (const float*)d_in[1];
    float* out = (float*)d_out;

    static bool attr_set = false;
    if (!attr_set) {
        cudaFuncSetAttribute(k_screen, cudaFuncAttributeMaxDynamicSharedMemorySize, SM_K1_TOT);
        attr_set = true;
    }

    k_enorm<<<KK / 256, 256>>>(cb);
    k_rx<<<NN / 256, 256>>>(x);
    k_ebf<<<(KK * DD) / 256, 256>>>(cb);
    k_screen<<<NN / 128, 256, SM_K1_TOT>>>(x);
    k_rescue<<<NN / 8, 256>>>(x, cb);
    k_out<<<dim3(NN / 256, DD / 8), 256>>>(x, cb, out);
    k_loss<<<1, 256>>>(out, out_size);
}